// round 14
// baseline (speedup 1.0000x reference)
#include <cuda_runtime.h>
#include <cuda_fp16.h>
#include <cstdint>

#define N0_   292864
#define N1_   11264
#define N2_   1024
#define F0_   25
#define F1_   10
#define D_IN_ 256
#define HID_  256
#define NCLS_ 47
#define KCAT_ 512
#define RPB   32      // rows per fused block

// ---------------- scratch ---------------------------------------------------
__device__ __half g_Bf[KCAT_ * HID_];   // B fp16, [k][n]
__device__ float g_H[N1_ * HID_];       // relu(layer0), compacted rows
__device__ float g_Bcat1[KCAT_ * NCLS_];
__device__ int   g_remap[N1_];
__device__ int   g_list[N1_];
__device__ int   g_cnt[1];

// ================= helpers =================================================
__device__ __forceinline__ uint32_t h2_u32(__half2 h) {
    return *reinterpret_cast<uint32_t*>(&h);
}
__device__ __forceinline__ uint32_t smem_u32(const void* p) {
    uint32_t a;
    asm("{ .reg .u64 t; cvta.to.shared.u64 t, %1; cvt.u32.u64 %0, t; }"
        : "=r"(a) : "l"(p));
    return a;
}
__device__ __forceinline__ void cp_async16(uint32_t dst, const void* src) {
    asm volatile("cp.async.cg.shared.global [%0], [%1], 16;"
                 :: "r"(dst), "l"(src) : "memory");
}
#define LDMX4(r, a)                                                            \
    asm volatile("ldmatrix.sync.aligned.m8n8.x4.shared.b16 {%0,%1,%2,%3}, [%4];" \
        : "=r"((r)[0]), "=r"((r)[1]), "=r"((r)[2]), "=r"((r)[3]) : "r"(a))
#define LDMX4T(r, a)                                                           \
    asm volatile("ldmatrix.sync.aligned.m8n8.x4.trans.shared.b16 {%0,%1,%2,%3}, [%4];" \
        : "=r"((r)[0]), "=r"((r)[1]), "=r"((r)[2]), "=r"((r)[3]) : "r"(a))

__device__ __forceinline__ void mma16816(float* c, const uint32_t* a,
                                         uint32_t b0, uint32_t b1) {
    asm volatile(
        "mma.sync.aligned.m16n8k16.row.col.f32.f16.f16.f32 "
        "{%0,%1,%2,%3}, {%4,%5,%6,%7}, {%8,%9}, {%0,%1,%2,%3};"
        : "+f"(c[0]), "+f"(c[1]), "+f"(c[2]), "+f"(c[3])
        : "r"(a[0]), "r"(a[1]), "r"(a[2]), "r"(a[3]), "r"(b0), "r"(b1));
}

// ================= prep: weights + remap init ==============================
__global__ void prep_init_kernel(const float* __restrict__ Ws0,
                                 const float* __restrict__ Wn0,
                                 const float* __restrict__ Ws1,
                                 const float* __restrict__ Wn1) {
    int idx = blockIdx.x * blockDim.x + threadIdx.x;
    if (idx < KCAT_ * HID_) {
        int k = idx / HID_, n = idx % HID_;
        float w = (k < D_IN_) ? Ws0[k * HID_ + n] : Wn0[(k - D_IN_) * HID_ + n];
        g_Bf[idx] = __float2half(w);
    }
    if (idx < KCAT_ * NCLS_) {
        int k = idx / NCLS_, n = idx % NCLS_;
        g_Bcat1[idx] = (k < HID_) ? Ws1[k * NCLS_ + n] : Wn1[(k - HID_) * NCLS_ + n];
    }
    if (idx < N1_) {
        g_remap[idx] = (idx < N2_) ? idx : -1;
        if (idx < N2_) g_list[idx] = idx;
    }
    if (idx == 0) g_cnt[0] = 0;
}

__global__ void mark_kernel(const int* __restrict__ nbr1) {
    int t = blockIdx.x * blockDim.x + threadIdx.x;
    if (t >= N2_ * F1_) return;
    int j = nbr1[t];
    if (j >= N2_) {
        if (atomicCAS(&g_remap[j], -1, -2) == -1) {
            int p = N2_ + atomicAdd(&g_cnt[0], 1);
            g_list[p] = j;
            g_remap[j] = p;
        }
    }
}

// ================= fused gather0 + gemm0 ===================================
// Per block: gather 32 dst rows (self + 25-neighbor mean) from emb directly
// into fp16 smem A tile, then fp16 mma GEMM against B (cp.async 2-stage).
// smem: [0,32K) A tile (32 rows x 1KB, swizzled)
//       [32K,96K) B stages 2 x 32KB (64k x 256n, swizzled)
//       [96K, +3328) indices [32][26]
#define SMF_B    32768
#define SMF_IDX  98304
#define SMF_TOT  (98304 + RPB * 26 * 4)

__device__ __forceinline__ void load_B(uint32_t sb, int stage, int kc, int tid) {
    uint32_t base = sb + SMF_B + stage * 32768;
#pragma unroll
    for (int i = 0; i < 8; i++) {
        int e = tid + i * 256;          // 2048 x 16B units
        int k = e >> 5, cg = e & 31;
        const __half* src = g_Bf + (size_t)(kc * 64 + k) * HID_ + cg * 8;
        uint32_t dst = base + k * 512 + (((cg & 24) | ((cg & 7) ^ (k & 7))) * 16);
        cp_async16(dst, src);
    }
    asm volatile("cp.async.commit_group;" ::: "memory");
}

__global__ __launch_bounds__(256, 2) void fused0_kernel(
    const int* __restrict__ gids0,
    const int* __restrict__ nbr0,
    const float* __restrict__ emb,
    const float* __restrict__ b0) {
    extern __shared__ char smem[];
    const int tid = threadIdx.x;
    const int b32 = blockIdx.x * RPB;
    const int ncount = N2_ + g_cnt[0];
    if (b32 >= ncount) return;

    const uint32_t sb = smem_u32(smem);
    int* sIdx = (int*)(smem + SMF_IDX);   // [32][26]

    // ---- B prefetch first: DMA overlaps the whole gather phase ----
    load_B(sb, 0, 0, tid);
    load_B(sb, 1, 1, tid);

    // ---- phase 0: resolve all 832 embedding row ids ----
    for (int e = tid; e < RPB * 26; e += 256) {
        int r = e / 26, j = e - r * 26;
        int i = g_list[b32 + r];
        int src = (j == 0) ? i : nbr0[i * F0_ + (j - 1)];
        sIdx[e] = gids0[src];
    }
    __syncthreads();

    // ---- phase 1: gather + mean -> fp16 smem A ----
    {
        int r  = tid >> 3;            // 0..31
        int l8 = tid & 7;
        const int* row_ids = sIdx + r * 26;
        float4 s[8], m[8];
        {
            const float4* p = (const float4*)(emb + (size_t)row_ids[0] * D_IN_);
#pragma unroll
            for (int q = 0; q < 8; q++) {
                s[q] = p[l8 + q * 8];
                m[q] = make_float4(0.f, 0.f, 0.f, 0.f);
            }
        }
#pragma unroll 5
        for (int j = 1; j < 26; j++) {
            const float4* p = (const float4*)(emb + (size_t)row_ids[j] * D_IN_);
#pragma unroll
            for (int q = 0; q < 8; q++) {
                float4 v = p[l8 + q * 8];
                m[q].x += v.x; m[q].y += v.y; m[q].z += v.z; m[q].w += v.w;
            }
        }
        const float sc = 1.0f / F0_;
        uint32_t arow = sb + r * 1024;
#pragma unroll
        for (int q = 0; q < 8; q++) {
            int f = (l8 + q * 8) * 4;             // feature index (mult of 4)
#pragma unroll
            for (int h = 0; h < 2; h++) {
                int k = h * 256 + f;
                int byte = k * 2;
                int u = byte >> 4;
                uint32_t addr = arow + (((u & 56) | ((u & 7) ^ (r & 7))) * 16)
                              + (byte & 15);
                uint2 val;
                if (h == 0) {
                    val.x = h2_u32(__floats2half2_rn(s[q].x, s[q].y));
                    val.y = h2_u32(__floats2half2_rn(s[q].z, s[q].w));
                } else {
                    val.x = h2_u32(__floats2half2_rn(m[q].x * sc, m[q].y * sc));
                    val.y = h2_u32(__floats2half2_rn(m[q].z * sc, m[q].w * sc));
                }
                asm volatile("st.shared.v2.b32 [%0], {%1, %2};"
                             :: "r"(addr), "r"(val.x), "r"(val.y));
            }
        }
    }
    __syncthreads();

    // ---- phase 2: GEMM 32x256 (fp16 mma), K=512 in 8 chunks of 64 ----
    const int lane = tid & 31;
    const int warp = tid >> 5;
    const int wn = warp * 32;

    float acc[2][4][4];
#pragma unroll
    for (int i = 0; i < 2; i++)
#pragma unroll
        for (int j = 0; j < 4; j++)
#pragma unroll
            for (int q = 0; q < 4; q++) acc[i][j][q] = 0.f;

#pragma unroll 1
    for (int cc = 0; cc < 8; cc++) {
        if (cc < 7) asm volatile("cp.async.wait_group 1;" ::: "memory");
        else        asm volatile("cp.async.wait_group 0;" ::: "memory");
        __syncthreads();
        uint32_t Bst = sb + SMF_B + (cc & 1) * 32768;
#pragma unroll
        for (int step = 0; step < 4; step++) {
            uint32_t a[2][4], bb[2][4];
#pragma unroll
            for (int mi = 0; mi < 2; mi++) {
                int rr = mi * 16 + (lane & 15);
                int c16 = cc * 8 + step * 2 + (lane >> 4);
                LDMX4(a[mi], sb + rr * 1024
                           + (((c16 & 56) | ((c16 & 7) ^ (rr & 7))) * 16));
            }
#pragma unroll
            for (int nb = 0; nb < 2; nb++) {
                int kk = step * 16 + (lane & 15);
                int cg = (wn >> 3) + nb * 2 + (lane >> 4);
                LDMX4T(bb[nb], Bst + kk * 512
                             + (((cg & 24) | ((cg & 7) ^ (kk & 7))) * 16));
            }
#pragma unroll
            for (int mi = 0; mi < 2; mi++)
#pragma unroll
                for (int ni = 0; ni < 4; ni++)
                    mma16816(acc[mi][ni], a[mi],
                             bb[ni >> 1][(ni & 1) * 2],
                             bb[ni >> 1][(ni & 1) * 2 + 1]);
        }
        __syncthreads();
        if (cc + 2 < 8) load_B(sb, cc & 1, cc + 2, tid);
        else asm volatile("cp.async.commit_group;" ::: "memory");
    }

    // ---- epilogue: bias + relu -> g_H ----
#pragma unroll
    for (int mi = 0; mi < 2; mi++) {
#pragma unroll
        for (int ni = 0; ni < 4; ni++) {
            int col = wn + ni * 8 + (lane & 3) * 2;
            float bx = __ldg(&b0[col]);
            float by = __ldg(&b0[col + 1]);
            int r0 = b32 + mi * 16 + (lane >> 2);
            float2 v0, v1;
            v0.x = fmaxf(acc[mi][ni][0] + bx, 0.f);
            v0.y = fmaxf(acc[mi][ni][1] + by, 0.f);
            v1.x = fmaxf(acc[mi][ni][2] + bx, 0.f);
            v1.y = fmaxf(acc[mi][ni][3] + by, 0.f);
            *(float2*)&g_H[(size_t)r0 * HID_ + col]       = v0;
            *(float2*)&g_H[(size_t)(r0 + 8) * HID_ + col] = v1;
        }
    }
}

// ================= fused layer-1: gather + mean + GEMM + bias ==============
__global__ __launch_bounds__(256) void layer1_kernel(
    const int* __restrict__ nbr1,
    const float* __restrict__ b1,
    float* __restrict__ out) {
    int i = blockIdx.x;
    int t = threadIdx.x;

    __shared__ float hcat[KCAT_];
    __shared__ float part[4][NCLS_];
    __shared__ int sp[F1_];

    if (t < F1_) sp[t] = g_remap[nbr1[i * F1_ + t]];
    __syncthreads();

    {
        float acc = 0.f;
#pragma unroll
        for (int j = 0; j < F1_; j++) acc += g_H[(size_t)sp[j] * HID_ + t];
        hcat[t]        = g_H[(size_t)i * HID_ + t];
        hcat[HID_ + t] = acc * (1.0f / F1_);
    }
    __syncthreads();

    if (t < NCLS_ * 4) {
        int c = t % NCLS_;
        int q = t / NCLS_;
        const float* B = g_Bcat1 + c;
        float acc = 0.f;
        int k0 = q * 128;
#pragma unroll 4
        for (int k = 0; k < 128; k++)
            acc += hcat[k0 + k] * B[(size_t)(k0 + k) * NCLS_];
        part[q][c] = acc;
    }
    __syncthreads();

    if (t < NCLS_) {
        out[i * NCLS_ + t] = b1[t] + ((part[0][t] + part[1][t])
                                    + (part[2][t] + part[3][t]));
    }
}

// ================= launch ===================================================
extern "C" void kernel_launch(void* const* d_in, const int* in_sizes, int n_in,
                              void* d_out, int out_size) {
    const int*   gids0 = (const int*)d_in[0];
    const int*   nbr0  = (const int*)d_in[1];
    const int*   nbr1  = (const int*)d_in[2];
    const float* emb   = (const float*)d_in[3];
    const float* Ws0   = (const float*)d_in[4];
    const float* Wn0   = (const float*)d_in[5];
    const float* b0    = (const float*)d_in[6];
    const float* Ws1   = (const float*)d_in[7];
    const float* Wn1   = (const float*)d_in[8];
    const float* b1    = (const float*)d_in[9];
    float* out = (float*)d_out;

    cudaFuncSetAttribute(fused0_kernel,
                         cudaFuncAttributeMaxDynamicSharedMemorySize, SMF_TOT);

    prep_init_kernel<<<(KCAT_ * HID_ + 255) / 256, 256>>>(Ws0, Wn0, Ws1, Wn1);
    mark_kernel<<<(N2_ * F1_ + 255) / 256, 256>>>(nbr1);
    fused0_kernel<<<N1_ / RPB, 256, SMF_TOT>>>(gids0, nbr0, emb, b0);
    layer1_kernel<<<N2_, 256>>>(nbr1, b1, out);
}

// round 15
// speedup vs baseline: 1.4049x; 1.4049x over previous
#include <cuda_runtime.h>
#include <cuda_fp16.h>
#include <cstdint>

#define N0_   292864
#define N1_   11264
#define N2_   1024
#define F0_   25
#define F1_   10
#define D_IN_ 256
#define HID_  256
#define NCLS_ 47
#define KCAT_ 512

// ---------------- scratch (device globals; no allocation allowed) ----------
__device__ __half g_Af[N1_ * KCAT_];    // A fp16 (compacted rows)
__device__ __half g_Bf[KCAT_ * HID_];   // B fp16, [k][n]
__device__ float g_H[N1_ * HID_];       // relu(layer0), compacted rows
__device__ float g_B1T[NCLS_ * KCAT_];  // layer-1 weights, [c][k]
__device__ int   g_remap[N1_];
__device__ int   g_list[N1_];
__device__ int   g_cnt[1];

// ================= helpers =================================================
__device__ __forceinline__ uint32_t smem_u32(const void* p) {
    uint32_t a;
    asm("{ .reg .u64 t; cvta.to.shared.u64 t, %1; cvt.u32.u64 %0, t; }"
        : "=r"(a) : "l"(p));
    return a;
}
__device__ __forceinline__ void cp_async16(uint32_t dst, const void* src) {
    asm volatile("cp.async.cg.shared.global [%0], [%1], 16;"
                 :: "r"(dst), "l"(src) : "memory");
}
#define LDMX4(r, a)                                                            \
    asm volatile("ldmatrix.sync.aligned.m8n8.x4.shared.b16 {%0,%1,%2,%3}, [%4];" \
        : "=r"((r)[0]), "=r"((r)[1]), "=r"((r)[2]), "=r"((r)[3]) : "r"(a))
#define LDMX4T(r, a)                                                           \
    asm volatile("ldmatrix.sync.aligned.m8n8.x4.trans.shared.b16 {%0,%1,%2,%3}, [%4];" \
        : "=r"((r)[0]), "=r"((r)[1]), "=r"((r)[2]), "=r"((r)[3]) : "r"(a))

__device__ __forceinline__ void mma16816(float* c, const uint32_t* a,
                                         uint32_t b0, uint32_t b1) {
    asm volatile(
        "mma.sync.aligned.m16n8k16.row.col.f32.f16.f16.f32 "
        "{%0,%1,%2,%3}, {%4,%5,%6,%7}, {%8,%9}, {%0,%1,%2,%3};"
        : "+f"(c[0]), "+f"(c[1]), "+f"(c[2]), "+f"(c[3])
        : "r"(a[0]), "r"(a[1]), "r"(a[2]), "r"(a[3]), "r"(b0), "r"(b1));
}

// ================= prep: weights + remap init ==============================
__global__ void prep_init_kernel(const float* __restrict__ Ws0,
                                 const float* __restrict__ Wn0,
                                 const float* __restrict__ Ws1,
                                 const float* __restrict__ Wn1) {
    int idx = blockIdx.x * blockDim.x + threadIdx.x;
    if (idx < KCAT_ * HID_) {
        int k = idx / HID_, n = idx % HID_;
        float w = (k < D_IN_) ? Ws0[k * HID_ + n] : Wn0[(k - D_IN_) * HID_ + n];
        g_Bf[idx] = __float2half(w);
    }
    if (idx < NCLS_ * KCAT_) {
        int c = idx / KCAT_, k = idx % KCAT_;
        g_B1T[idx] = (k < HID_) ? Ws1[k * NCLS_ + c] : Wn1[(k - HID_) * NCLS_ + c];
    }
    if (idx < N1_) {
        g_remap[idx] = (idx < N2_) ? idx : -1;
        if (idx < N2_) g_list[idx] = idx;
    }
    if (idx == 0) g_cnt[0] = 0;
}

__global__ void mark_kernel(const int* __restrict__ nbr1) {
    int t = blockIdx.x * blockDim.x + threadIdx.x;
    if (t >= N2_ * F1_) return;
    int j = nbr1[t];
    if (j >= N2_) {
        if (atomicCAS(&g_remap[j], -1, -2) == -1) {
            int p = N2_ + atomicAdd(&g_cnt[0], 1);
            g_list[p] = j;
            g_remap[j] = p;
        }
    }
}

// ================= layer-0 gather + mean -> fp16 (compacted) ===============
__global__ __launch_bounds__(256) void gather0_kernel(
    const int* __restrict__ gids0,
    const int* __restrict__ nbr0,
    const float* __restrict__ emb) {
    int tid = threadIdx.x;
    int sub = tid >> 6;
    int lt  = tid & 63;
    int b   = blockIdx.x * 4 + sub;
    int ncount = N2_ + g_cnt[0];
    bool active = (b < ncount);

    __shared__ int sg[4][F0_];
    __shared__ int sdst[4];

    int i = active ? g_list[b] : 0;
    if (active && lt < F0_) sg[sub][lt] = gids0[nbr0[i * F0_ + lt]];
    if (active && lt == 32) sdst[sub] = gids0[i];
    __syncthreads();

    if (!active) return;

    int ft = lt * 4;
    float4 xd = *(const float4*)&emb[(size_t)sdst[sub] * D_IN_ + ft];

    float4 acc = make_float4(0.f, 0.f, 0.f, 0.f);
#pragma unroll
    for (int j = 0; j < F0_; j++) {
        float4 v = *(const float4*)&emb[(size_t)sg[sub][j] * D_IN_ + ft];
        acc.x += v.x; acc.y += v.y; acc.z += v.z; acc.w += v.w;
    }
    const float s = 1.0f / F0_;

    __half2 d01 = __floats2half2_rn(xd.x, xd.y);
    __half2 d23 = __floats2half2_rn(xd.z, xd.w);
    __half2 a01 = __floats2half2_rn(acc.x * s, acc.y * s);
    __half2 a23 = __floats2half2_rn(acc.z * s, acc.w * s);

    size_t base = (size_t)b * KCAT_;
    *(__half2*)&g_Af[base + ft]             = d01;
    *(__half2*)&g_Af[base + ft + 2]         = d23;
    *(__half2*)&g_Af[base + D_IN_ + ft]     = a01;
    *(__half2*)&g_Af[base + D_IN_ + ft + 2] = a23;
}

// ================= layer-0 GEMM: single-pass fp16 mma ======================
#define SM_STAGE 32768
#define SM_TOTAL (4 * SM_STAGE)

__device__ __forceinline__ void load_chunk(uint32_t sb, int buf,
                                           int bm, int bn, int kc, int tid) {
    uint32_t base = sb + buf * SM_STAGE;
#pragma unroll
    for (int i = 0; i < 4; i++) {
        int idx = tid + i * 256;
        {
            int row = idx >> 3, c16 = idx & 7;
            size_t so = (size_t)(bm + row) * KCAT_ + kc * 64 + c16 * 8;
            uint32_t doff = row * 128 + ((c16 ^ (row & 7)) * 16);
            cp_async16(base + doff, g_Af + so);
        }
        {
            int k = idx >> 4, c = idx & 15;
            size_t so = (size_t)(kc * 64 + k) * HID_ + bn + c * 8;
            uint32_t doff = k * 256 + (c >> 3) * 128 + (((c & 7) ^ (k & 7)) * 16);
            cp_async16(base + 16384 + doff, g_Bf + so);
        }
    }
    asm volatile("cp.async.commit_group;" ::: "memory");
}

__device__ __forceinline__ void compute_chunk(uint32_t sb, int buf, int wm,
                                              int wn, int lane,
                                              float acc[4][4][4]) {
    uint32_t As = sb + buf * SM_STAGE;
    uint32_t Bs = As + 16384;
#pragma unroll
    for (int step = 0; step < 4; step++) {
        uint32_t a[4][4], b[2][4];
#pragma unroll
        for (int mi = 0; mi < 4; mi++) {
            int row = wm + mi * 16 + (lane & 15);
            int c16 = 2 * step + (lane >> 4);
            LDMX4(a[mi], As + row * 128 + ((c16 ^ (row & 7)) * 16));
        }
#pragma unroll
        for (int nb = 0; nb < 2; nb++) {
            int k  = step * 16 + (lane & 15);
            int cg = ((wn + nb * 16) >> 3) + (lane >> 4);
            LDMX4T(b[nb], Bs + k * 256 + (cg >> 3) * 128
                         + (((cg & 7) ^ (k & 7)) * 16));
        }
#pragma unroll
        for (int mi = 0; mi < 4; mi++)
#pragma unroll
            for (int ni = 0; ni < 4; ni++)
                mma16816(acc[mi][ni], a[mi],
                         b[ni >> 1][(ni & 1) * 2],
                         b[ni >> 1][(ni & 1) * 2 + 1]);
    }
}

__global__ __launch_bounds__(256) void gemm0_mma_kernel(const float* __restrict__ b0) {
    extern __shared__ char smem[];
    const int bm = blockIdx.x * 128;
    {
        int ncount = N2_ + g_cnt[0];
        if (bm >= ncount) return;
    }
    const uint32_t sb = smem_u32(smem);
    const int tid  = threadIdx.x;
    const int lane = tid & 31;
    const int warp = tid >> 5;
    const int wm = (warp & 1) * 64;
    const int wn = (warp >> 1) * 32;
    const int bn = blockIdx.y * 128;

    float acc[4][4][4];
#pragma unroll
    for (int i = 0; i < 4; i++)
#pragma unroll
        for (int j = 0; j < 4; j++)
#pragma unroll
            for (int q = 0; q < 4; q++) acc[i][j][q] = 0.f;

    const int NCH = KCAT_ / 64;  // 8
    load_chunk(sb, 0, bm, bn, 0, tid);
    load_chunk(sb, 1, bm, bn, 1, tid);
    load_chunk(sb, 2, bm, bn, 2, tid);

#pragma unroll 1
    for (int cc = 0; cc < NCH; cc++) {
        asm volatile("cp.async.wait_group 2;" ::: "memory");
        __syncthreads();
        int nc = cc + 3;
        if (nc < NCH) load_chunk(sb, nc & 3, bm, bn, nc, tid);
        else asm volatile("cp.async.commit_group;" ::: "memory");
        compute_chunk(sb, cc & 3, wm, wn, lane, acc);
    }

    // epilogue: bias + relu -> g_H (fp32, compacted rows)
#pragma unroll
    for (int mi = 0; mi < 4; mi++) {
#pragma unroll
        for (int ni = 0; ni < 4; ni++) {
            int col = bn + wn + ni * 8 + (lane & 3) * 2;
            float bx = __ldg(&b0[col]);
            float by = __ldg(&b0[col + 1]);
            int r0 = bm + wm + mi * 16 + (lane >> 2);
            float2 v0, v1;
            v0.x = fmaxf(acc[mi][ni][0] + bx, 0.f);
            v0.y = fmaxf(acc[mi][ni][1] + by, 0.f);
            v1.x = fmaxf(acc[mi][ni][2] + bx, 0.f);
            v1.y = fmaxf(acc[mi][ni][3] + by, 0.f);
            *(float2*)&g_H[(size_t)r0 * HID_ + col]       = v0;
            *(float2*)&g_H[(size_t)(r0 + 8) * HID_ + col] = v1;
        }
    }
}

// ================= fused layer-1: gather + mean + GEMM (warp dot) ==========
// One block per dst row. hcat[512] in smem; warp w handles classes {w, w+8,..};
// lane l covers k = 4l + 128q (q<4) with float4s -> conflict-free, coalesced.
__global__ __launch_bounds__(256) void layer1_kernel(
    const int* __restrict__ nbr1,
    const float* __restrict__ b1,
    float* __restrict__ out) {
    int i = blockIdx.x;
    int t = threadIdx.x;

    __shared__ float hcat[KCAT_];
    __shared__ int sp[F1_];

    if (t < F1_) sp[t] = g_remap[nbr1[i * F1_ + t]];
    __syncthreads();

    {
        float acc = 0.f;
#pragma unroll
        for (int j = 0; j < F1_; j++) acc += g_H[(size_t)sp[j] * HID_ + t];
        hcat[t]        = g_H[(size_t)i * HID_ + t];
        hcat[HID_ + t] = acc * (1.0f / F1_);
    }
    __syncthreads();

    int w = t >> 5, l = t & 31;
    const float4* H4 = (const float4*)hcat;
#pragma unroll 1
    for (int c = w; c < NCLS_; c += 8) {
        const float4* B4 = (const float4*)(g_B1T + (size_t)c * KCAT_);
        float s = 0.f;
#pragma unroll
        for (int q = 0; q < 4; q++) {
            float4 hv = H4[l + 32 * q];
            float4 bv = B4[l + 32 * q];
            s += hv.x * bv.x + hv.y * bv.y + hv.z * bv.z + hv.w * bv.w;
        }
#pragma unroll
        for (int off = 16; off; off >>= 1)
            s += __shfl_xor_sync(0xFFFFFFFFu, s, off);
        if (l == 0) out[i * NCLS_ + c] = s + b1[c];
    }
}

// ================= launch ===================================================
extern "C" void kernel_launch(void* const* d_in, const int* in_sizes, int n_in,
                              void* d_out, int out_size) {
    const int*   gids0 = (const int*)d_in[0];
    const int*   nbr0  = (const int*)d_in[1];
    const int*   nbr1  = (const int*)d_in[2];
    const float* emb   = (const float*)d_in[3];
    const float* Ws0   = (const float*)d_in[4];
    const float* Wn0   = (const float*)d_in[5];
    const float* b0    = (const float*)d_in[6];
    const float* Ws1   = (const float*)d_in[7];
    const float* Wn1   = (const float*)d_in[8];
    const float* b1    = (const float*)d_in[9];
    float* out = (float*)d_out;

    cudaFuncSetAttribute(gemm0_mma_kernel,
                         cudaFuncAttributeMaxDynamicSharedMemorySize, SM_TOTAL);

    prep_init_kernel<<<(KCAT_ * HID_ + 255) / 256, 256>>>(Ws0, Wn0, Ws1, Wn1);
    mark_kernel<<<(N2_ * F1_ + 255) / 256, 256>>>(nbr1);
    gather0_kernel<<<(N1_ + 3) / 4, 256>>>(gids0, nbr0, emb);
    gemm0_mma_kernel<<<dim3(N1_ / 128, HID_ / 128), 256, SM_TOTAL>>>(b0);
    layer1_kernel<<<N2_, 256>>>(nbr1, b1, out);
}

// round 16
// speedup vs baseline: 1.4444x; 1.0281x over previous
#include <cuda_runtime.h>
#include <cuda_fp16.h>
#include <cstdint>

#define N0_   292864
#define N1_   11264
#define N2_   1024
#define F0_   25
#define F1_   10
#define D_IN_ 256
#define HID_  256
#define NCLS_ 47
#define KCAT_ 512

// ---------------- scratch (device globals; no allocation allowed) ----------
__device__ __half g_Af[N1_ * KCAT_];    // A fp16 (compacted rows)
__device__ __half g_Bf[KCAT_ * HID_];   // B fp16, [k][n]
__device__ float g_H[N1_ * HID_];       // relu(layer0), compacted rows
__device__ float g_B1T[NCLS_ * KCAT_];  // layer-1 weights, [c][k]
__device__ int   g_remap[N1_];
__device__ int   g_list[N1_];
__device__ int   g_cnt[1];

// ================= helpers =================================================
__device__ __forceinline__ uint32_t smem_u32(const void* p) {
    uint32_t a;
    asm("{ .reg .u64 t; cvta.to.shared.u64 t, %1; cvt.u32.u64 %0, t; }"
        : "=r"(a) : "l"(p));
    return a;
}
__device__ __forceinline__ void cp_async16(uint32_t dst, const void* src) {
    asm volatile("cp.async.cg.shared.global [%0], [%1], 16;"
                 :: "r"(dst), "l"(src) : "memory");
}
#define LDMX4(r, a)                                                            \
    asm volatile("ldmatrix.sync.aligned.m8n8.x4.shared.b16 {%0,%1,%2,%3}, [%4];" \
        : "=r"((r)[0]), "=r"((r)[1]), "=r"((r)[2]), "=r"((r)[3]) : "r"(a))
#define LDMX4T(r, a)                                                           \
    asm volatile("ldmatrix.sync.aligned.m8n8.x4.trans.shared.b16 {%0,%1,%2,%3}, [%4];" \
        : "=r"((r)[0]), "=r"((r)[1]), "=r"((r)[2]), "=r"((r)[3]) : "r"(a))

__device__ __forceinline__ void mma16816(float* c, const uint32_t* a,
                                         uint32_t b0, uint32_t b1) {
    asm volatile(
        "mma.sync.aligned.m16n8k16.row.col.f32.f16.f16.f32 "
        "{%0,%1,%2,%3}, {%4,%5,%6,%7}, {%8,%9}, {%0,%1,%2,%3};"
        : "+f"(c[0]), "+f"(c[1]), "+f"(c[2]), "+f"(c[3])
        : "r"(a[0]), "r"(a[1]), "r"(a[2]), "r"(a[3]), "r"(b0), "r"(b1));
}

// ================= prep: weights + remap init ==============================
__global__ void prep_init_kernel(const float* __restrict__ Ws0,
                                 const float* __restrict__ Wn0,
                                 const float* __restrict__ Ws1,
                                 const float* __restrict__ Wn1) {
    int idx = blockIdx.x * blockDim.x + threadIdx.x;
    if (idx < KCAT_ * HID_) {
        int k = idx / HID_, n = idx % HID_;
        float w = (k < D_IN_) ? Ws0[k * HID_ + n] : Wn0[(k - D_IN_) * HID_ + n];
        g_Bf[idx] = __float2half(w);
    }
    if (idx < NCLS_ * KCAT_) {
        int c = idx / KCAT_, k = idx % KCAT_;
        g_B1T[idx] = (k < HID_) ? Ws1[k * NCLS_ + c] : Wn1[(k - HID_) * NCLS_ + c];
    }
    if (idx < N1_) {
        g_remap[idx] = (idx < N2_) ? idx : -1;
        if (idx < N2_) g_list[idx] = idx;
    }
    if (idx == 0) g_cnt[0] = 0;
}

__global__ void mark_kernel(const int* __restrict__ nbr1) {
    int t = blockIdx.x * blockDim.x + threadIdx.x;
    if (t >= N2_ * F1_) return;
    int j = nbr1[t];
    if (j >= N2_) {
        if (atomicCAS(&g_remap[j], -1, -2) == -1) {
            int p = N2_ + atomicAdd(&g_cnt[0], 1);
            g_list[p] = j;
            g_remap[j] = p;
        }
    }
}

// ================= layer-0 gather + mean -> fp16 (compacted) ===============
__global__ __launch_bounds__(256) void gather0_kernel(
    const int* __restrict__ gids0,
    const int* __restrict__ nbr0,
    const float* __restrict__ emb) {
    int tid = threadIdx.x;
    int sub = tid >> 6;
    int lt  = tid & 63;
    int b   = blockIdx.x * 4 + sub;
    int ncount = N2_ + g_cnt[0];
    bool active = (b < ncount);

    __shared__ int sg[4][F0_];
    __shared__ int sdst[4];

    int i = active ? g_list[b] : 0;
    if (active && lt < F0_) sg[sub][lt] = gids0[nbr0[i * F0_ + lt]];
    if (active && lt == 32) sdst[sub] = gids0[i];
    __syncthreads();

    if (!active) return;

    int ft = lt * 4;
    float4 xd = *(const float4*)&emb[(size_t)sdst[sub] * D_IN_ + ft];

    float4 acc = make_float4(0.f, 0.f, 0.f, 0.f);
#pragma unroll
    for (int j = 0; j < F0_; j++) {
        float4 v = *(const float4*)&emb[(size_t)sg[sub][j] * D_IN_ + ft];
        acc.x += v.x; acc.y += v.y; acc.z += v.z; acc.w += v.w;
    }
    const float s = 1.0f / F0_;

    __half2 d01 = __floats2half2_rn(xd.x, xd.y);
    __half2 d23 = __floats2half2_rn(xd.z, xd.w);
    __half2 a01 = __floats2half2_rn(acc.x * s, acc.y * s);
    __half2 a23 = __floats2half2_rn(acc.z * s, acc.w * s);

    size_t base = (size_t)b * KCAT_;
    *(__half2*)&g_Af[base + ft]             = d01;
    *(__half2*)&g_Af[base + ft + 2]         = d23;
    *(__half2*)&g_Af[base + D_IN_ + ft]     = a01;
    *(__half2*)&g_Af[base + D_IN_ + ft + 2] = a23;
}

// ================= layer-0 GEMM: 64x128 tiles, occ-2 fp16 mma ==============
// stage = A(64x64k, 8KB) + B(64k x 128n, 16KB) = 24KB; 4 stages = 96KB
#define SM_ASZ   8192
#define SM_STAGE 24576
#define SM_TOTAL (4 * SM_STAGE)

__device__ __forceinline__ void load_chunk(uint32_t sb, int buf,
                                           int bm, int bn, int kc, int tid) {
    uint32_t base = sb + buf * SM_STAGE;
    // A: 64 rows x 64 k (128B/row), swizzled; 512 x 16B units
#pragma unroll
    for (int i = 0; i < 2; i++) {
        int idx = tid + i * 256;
        int row = idx >> 3, c16 = idx & 7;
        size_t so = (size_t)(bm + row) * KCAT_ + kc * 64 + c16 * 8;
        uint32_t doff = row * 128 + ((c16 ^ (row & 7)) * 16);
        cp_async16(base + doff, g_Af + so);
    }
    // B: 64 k-rows x 128 n (256B/row, two 128B atoms); 1024 x 16B units
#pragma unroll
    for (int i = 0; i < 4; i++) {
        int idx = tid + i * 256;
        int k = idx >> 4, c = idx & 15;
        size_t so = (size_t)(kc * 64 + k) * HID_ + bn + c * 8;
        uint32_t doff = k * 256 + (c >> 3) * 128 + (((c & 7) ^ (k & 7)) * 16);
        cp_async16(base + SM_ASZ + doff, g_Bf + so);
    }
    asm volatile("cp.async.commit_group;" ::: "memory");
}

__device__ __forceinline__ void compute_chunk(uint32_t sb, int buf, int wm,
                                              int wn, int lane,
                                              float acc[2][4][4]) {
    uint32_t As = sb + buf * SM_STAGE;
    uint32_t Bs = As + SM_ASZ;
#pragma unroll
    for (int step = 0; step < 4; step++) {
        uint32_t a[2][4], b[2][4];
#pragma unroll
        for (int mi = 0; mi < 2; mi++) {
            int row = wm + mi * 16 + (lane & 15);
            int c16 = 2 * step + (lane >> 4);
            LDMX4(a[mi], As + row * 128 + ((c16 ^ (row & 7)) * 16));
        }
#pragma unroll
        for (int nb = 0; nb < 2; nb++) {
            int k  = step * 16 + (lane & 15);
            int cg = ((wn + nb * 16) >> 3) + (lane >> 4);
            LDMX4T(b[nb], Bs + k * 256 + (cg >> 3) * 128
                         + (((cg & 7) ^ (k & 7)) * 16));
        }
#pragma unroll
        for (int mi = 0; mi < 2; mi++)
#pragma unroll
            for (int ni = 0; ni < 4; ni++)
                mma16816(acc[mi][ni], a[mi],
                         b[ni >> 1][(ni & 1) * 2],
                         b[ni >> 1][(ni & 1) * 2 + 1]);
    }
}

__global__ __launch_bounds__(256, 2) void gemm0_mma_kernel(const float* __restrict__ b0) {
    extern __shared__ char smem[];
    const int bm = blockIdx.x * 64;
    {
        int ncount = N2_ + g_cnt[0];
        if (bm >= ncount) return;
    }
    const uint32_t sb = smem_u32(smem);
    const int tid  = threadIdx.x;
    const int lane = tid & 31;
    const int warp = tid >> 5;
    const int wm = (warp & 1) * 32;
    const int wn = (warp >> 1) * 32;
    const int bn = blockIdx.y * 128;

    float acc[2][4][4];
#pragma unroll
    for (int i = 0; i < 2; i++)
#pragma unroll
        for (int j = 0; j < 4; j++)
#pragma unroll
            for (int q = 0; q < 4; q++) acc[i][j][q] = 0.f;

    const int NCH = KCAT_ / 64;  // 8
    load_chunk(sb, 0, bm, bn, 0, tid);
    load_chunk(sb, 1, bm, bn, 1, tid);
    load_chunk(sb, 2, bm, bn, 2, tid);

#pragma unroll 1
    for (int cc = 0; cc < NCH; cc++) {
        asm volatile("cp.async.wait_group 2;" ::: "memory");
        __syncthreads();
        int nc = cc + 3;
        if (nc < NCH) load_chunk(sb, nc & 3, bm, bn, nc, tid);
        else asm volatile("cp.async.commit_group;" ::: "memory");
        compute_chunk(sb, cc & 3, wm, wn, lane, acc);
    }

    // epilogue: bias + relu -> g_H (fp32, compacted rows)
#pragma unroll
    for (int mi = 0; mi < 2; mi++) {
#pragma unroll
        for (int ni = 0; ni < 4; ni++) {
            int col = bn + wn + ni * 8 + (lane & 3) * 2;
            float bx = __ldg(&b0[col]);
            float by = __ldg(&b0[col + 1]);
            int r0 = bm + wm + mi * 16 + (lane >> 2);
            float2 v0, v1;
            v0.x = fmaxf(acc[mi][ni][0] + bx, 0.f);
            v0.y = fmaxf(acc[mi][ni][1] + by, 0.f);
            v1.x = fmaxf(acc[mi][ni][2] + bx, 0.f);
            v1.y = fmaxf(acc[mi][ni][3] + by, 0.f);
            *(float2*)&g_H[(size_t)r0 * HID_ + col]       = v0;
            *(float2*)&g_H[(size_t)(r0 + 8) * HID_ + col] = v1;
        }
    }
}

// ================= fused layer-1: gather + mean + GEMM (warp dot) ==========
__global__ __launch_bounds__(256) void layer1_kernel(
    const int* __restrict__ nbr1,
    const float* __restrict__ b1,
    float* __restrict__ out) {
    int i = blockIdx.x;
    int t = threadIdx.x;

    __shared__ float hcat[KCAT_];
    __shared__ int sp[F1_];

    if (t < F1_) sp[t] = g_remap[nbr1[i * F1_ + t]];
    __syncthreads();

    {
        float acc = 0.f;
#pragma unroll
        for (int j = 0; j < F1_; j++) acc += g_H[(size_t)sp[j] * HID_ + t];
        hcat[t]        = g_H[(size_t)i * HID_ + t];
        hcat[HID_ + t] = acc * (1.0f / F1_);
    }
    __syncthreads();

    int w = t >> 5, l = t & 31;
    const float4* H4 = (const float4*)hcat;
#pragma unroll 1
    for (int c = w; c < NCLS_; c += 8) {
        const float4* B4 = (const float4*)(g_B1T + (size_t)c * KCAT_);
        float s = 0.f;
#pragma unroll
        for (int q = 0; q < 4; q++) {
            float4 hv = H4[l + 32 * q];
            float4 bv = B4[l + 32 * q];
            s += hv.x * bv.x + hv.y * bv.y + hv.z * bv.z + hv.w * bv.w;
        }
#pragma unroll
        for (int off = 16; off; off >>= 1)
            s += __shfl_xor_sync(0xFFFFFFFFu, s, off);
        if (l == 0) out[i * NCLS_ + c] = s + b1[c];
    }
}

// ================= launch ===================================================
extern "C" void kernel_launch(void* const* d_in, const int* in_sizes, int n_in,
                              void* d_out, int out_size) {
    const int*   gids0 = (const int*)d_in[0];
    const int*   nbr0  = (const int*)d_in[1];
    const int*   nbr1  = (const int*)d_in[2];
    const float* emb   = (const float*)d_in[3];
    const float* Ws0   = (const float*)d_in[4];
    const float* Wn0   = (const float*)d_in[5];
    const float* b0    = (const float*)d_in[6];
    const float* Ws1   = (const float*)d_in[7];
    const float* Wn1   = (const float*)d_in[8];
    const float* b1    = (const float*)d_in[9];
    float* out = (float*)d_out;

    cudaFuncSetAttribute(gemm0_mma_kernel,
                         cudaFuncAttributeMaxDynamicSharedMemorySize, SM_TOTAL);

    prep_init_kernel<<<(KCAT_ * HID_ + 255) / 256, 256>>>(Ws0, Wn0, Ws1, Wn1);
    mark_kernel<<<(N2_ * F1_ + 255) / 256, 256>>>(nbr1);
    gather0_kernel<<<(N1_ + 3) / 4, 256>>>(gids0, nbr0, emb);
    gemm0_mma_kernel<<<dim3(N1_ / 64, HID_ / 128), 256, SM_TOTAL>>>(b0);
    layer1_kernel<<<N2_, 256>>>(nbr1, b1, out);
}